// round 10
// baseline (speedup 1.0000x reference)
#include <cuda_runtime.h>
#include <cuda_fp16.h>
#include <math.h>

constexpr int Bq   = 4;
constexpr int Nq   = 64;
constexpr int Fq   = 64;
constexpr int FINq = 32;
constexpr int EDIMq= 32;
constexpr int FFq  = Fq * Fq;          // 4096
constexpr int ROWS = Bq * Nq;          // 256 target rows (b,n)

constexpr int NSTAGE = 4;              // cp.async pipeline stages
constexpr int CHUNK_BYTES = 16384;     // 2 edges * 8KB

__device__ float  g_H[ROWS * Fq];      // H0 then ping
__device__ float  g_H2[ROWS * Fq];
__device__ float  g_agg1[ROWS * Fq];   // round-1 aggregates (from k_edge)
__device__ int    g_cnt[ROWS];
__device__ int    g_midx[ROWS * Nq];
// Interleaved: per active slot 2048 half2; entry c (c = ii*64+j, ii<32)
// holds (A[ii][j], A[ii+32][j]). Inactive slots stay zero (never written).
__device__ __align__(16) __half2 g_Amat[(size_t)ROWS * Nq * (FFq / 2)];

__device__ __forceinline__ float sigm(float x) { return 1.0f / (1.0f + expf(-x)); }
__device__ __forceinline__ __half2 h2(unsigned int u) {
    return *reinterpret_cast<__half2*>(&u);
}
__device__ __forceinline__ unsigned long long pack2(float lo, float hi) {
    unsigned long long r;
    asm("mov.b64 %0, {%1, %2};" : "=l"(r) : "f"(lo), "f"(hi));
    return r;
}
__device__ __forceinline__ void unpack2(unsigned long long v, float& lo, float& hi) {
    asm("mov.b64 {%0, %1}, %2;" : "=f"(lo), "=f"(hi) : "l"(v));
}
__device__ __forceinline__ unsigned long long ffma2(
    unsigned long long a, unsigned long long b, unsigned long long c) {
    unsigned long long d;
    asm("fma.rn.f32x2 %0, %1, %2, %3;" : "=l"(d) : "l"(a), "l"(b), "l"(c));
    return d;
}
__device__ __forceinline__ void cp_async16(void* smem_ptr, const void* gptr) {
    unsigned sa = (unsigned)__cvta_generic_to_shared(smem_ptr);
    asm volatile("cp.async.cg.shared.global [%0], [%1], 16;" :: "r"(sa), "l"(gptr));
}
__device__ __forceinline__ void cp_commit() {
    asm volatile("cp.async.commit_group;");
}
template<int N> __device__ __forceinline__ void cp_wait() {
    asm volatile("cp.async.wait_group %0;" :: "n"(N));
}

// ---------------------------------------------------------------------------
// Kernel 1 (mega): compaction + embedding + edge MLP + ROUND-1 AGGREGATION.
// Block (rp, by): rows {2rp, 2rp+1} x column set {c0..c0+255} U {+2048}.
// Dynamic smem: Es2 | Hs | s_m | s_cnt | red
// ---------------------------------------------------------------------------
constexpr int ESM_ES2  = 0;                       // 128*32 ull = 32768
constexpr int ESM_HS   = 32768;                   // 4096 float = 16384
constexpr int ESM_SM   = 49152;                   // 128 int    = 512
constexpr int ESM_CNT  = 49664;                   // 2 int      = 8 (pad 16)
constexpr int ESM_RED  = 49680;                   // 8*4 float  = 128
constexpr int ESM_TOTAL= 49824;

__global__ __launch_bounds__(256) void k_edge(
    const float* __restrict__ X, const float* __restrict__ A,
    const float* __restrict__ E,
    const float* __restrict__ W_embed, const float* __restrict__ b_embed,
    const float* __restrict__ W_edge, const float* __restrict__ b_edge)
{
    extern __shared__ __align__(16) char smem[];
    unsigned long long* Es2 = reinterpret_cast<unsigned long long*>(smem + ESM_ES2);
    float* Hs  = reinterpret_cast<float*>(smem + ESM_HS);
    int*   s_m = reinterpret_cast<int*>(smem + ESM_SM);
    int*   s_cnt = reinterpret_cast<int*>(smem + ESM_CNT);
    float* red = reinterpret_cast<float*>(smem + ESM_RED);

    int rp = blockIdx.x;
    int by = blockIdx.y;
    int c0 = by * 256;
    int t  = threadIdx.x;
    int b  = (rp * 2) >> 6;

    // ---- per-block ballot compaction (warp0: row0, warp1: row1) ----
    if (t < 64) {
        int r = t >> 5, lane = t & 31;
        int row = rp * 2 + r;
        const float* Arow = A + (size_t)row * Nq;
        unsigned a0 = (Arow[lane] > 0.5f) ? 1u : 0u;
        unsigned a1 = (Arow[32 + lane] > 0.5f) ? 1u : 0u;
        unsigned m0 = __ballot_sync(0xffffffffu, a0);
        unsigned m1 = __ballot_sync(0xffffffffu, a1);
        unsigned lm = (lane == 0) ? 0u : (0xffffffffu >> (32 - lane));
        int n0 = __popc(m0);
        if (a0) {
            int p = __popc(m0 & lm);
            s_m[r * 64 + p] = lane;
            if (by == 0) g_midx[row * Nq + p] = lane;
        }
        if (a1) {
            int p = n0 + __popc(m1 & lm);
            s_m[r * 64 + p] = 32 + lane;
            if (by == 0) g_midx[row * Nq + p] = 32 + lane;
        }
        if (lane == 0) {
            int c = n0 + __popc(m1);
            s_cnt[r] = c;
            if (by == 0) g_cnt[row] = c;
        }
    }
    __syncthreads();

    int cnt0 = s_cnt[0];
    int ne   = cnt0 + s_cnt[1];

    // ---- embedding for ALL 64 nodes of this batch (local) ----
    for (int idx = t; idx < Nq * Fq; idx += 256) {
        int m = idx >> 6, f = idx & 63;
        float acc = b_embed[f];
#pragma unroll
        for (int k = 0; k < FINq; k++)
            acc += X[((size_t)b * Nq + m) * FINq + k] * W_embed[k * Fq + f];
        Hs[idx] = fmaxf(acc, 0.0f);
    }

    // ---- E rows for active edges (duplicated-pair) ----
    for (int i = t; i < ne * EDIMq; i += 256) {
        int kk = i >> 5, e = i & 31;
        int p  = (kk >= cnt0) ? 1 : 0;
        int kl = kk - (p ? cnt0 : 0);
        int row = rp * 2 + p;
        int m  = s_m[p * 64 + kl];
        float v = E[((size_t)row * Nq + m) * EDIMq + e];
        Es2[kk * EDIMq + e] = pack2(v, v);
    }
    __syncthreads();

    // by==0 writes H0 for its 2 rows
    if (by == 0 && t < 128) {
        int r = t >> 6, f = t & 63;
        int row = rp * 2 + r;
        g_H[(size_t)row * Fq + f] = Hs[(row & 63) * Fq + f];
    }

    // ---- edge MLP + round-1 aggregation ----
    int c_a = c0 + t;            // ii*64+j, ii<32
    int c_b = c_a + 2048;
    int j = t & 63;
    unsigned long long w01[EDIMq];
#pragma unroll
    for (int e = 0; e < EDIMq; e++)
        w01[e] = pack2(W_edge[(size_t)e * FFq + c_a], W_edge[(size_t)e * FFq + c_b]);
    unsigned long long bias01 = pack2(b_edge[c_a], b_edge[c_b]);

    float r0lo = 0.0f, r0hi = 0.0f, r1lo = 0.0f, r1hi = 0.0f;

    auto emit = [&](int kk, unsigned long long acc) {
        float a0, a1;
        unpack2(acc, a0, a1);
        float al = fmaxf(a0, 0.0f), ah = fmaxf(a1, 0.0f);
        int p  = (kk >= cnt0) ? 1 : 0;
        int kl = kk - (p ? cnt0 : 0);
        int row = rp * 2 + p;
        int m  = s_m[p * 64 + kl];
        float h = Hs[m * Fq + j];
        float h0 = p ? 0.0f : h, h1v = p ? h : 0.0f;
        r0lo += al * h0; r0hi += ah * h0;
        r1lo += al * h1v; r1hi += ah * h1v;
        g_Amat[((size_t)row * Nq + kl) * (FFq / 2) + c_a] = __floats2half2_rn(al, ah);
    };

    int kk = 0;
    for (; kk + 2 <= ne; kk += 2) {
        unsigned long long acc0 = bias01, acc1 = bias01;
#pragma unroll
        for (int e = 0; e < EDIMq; e++) {
            acc0 = ffma2(Es2[kk * EDIMq + e],       w01[e], acc0);
            acc1 = ffma2(Es2[(kk + 1) * EDIMq + e], w01[e], acc1);
        }
        emit(kk, acc0);
        emit(kk + 1, acc1);
    }
    if (kk < ne) {
        unsigned long long acc0 = bias01;
#pragma unroll
        for (int e = 0; e < EDIMq; e++)
            acc0 = ffma2(Es2[kk * EDIMq + e], w01[e], acc0);
        emit(kk, acc0);
    }

    // ---- reduce agg over j (64 threads = 2 warps per ii-group) ----
#pragma unroll
    for (int ofs = 16; ofs > 0; ofs >>= 1) {
        r0lo += __shfl_xor_sync(0xffffffffu, r0lo, ofs);
        r0hi += __shfl_xor_sync(0xffffffffu, r0hi, ofs);
        r1lo += __shfl_xor_sync(0xffffffffu, r1lo, ofs);
        r1hi += __shfl_xor_sync(0xffffffffu, r1hi, ofs);
    }
    int wid = t >> 5;
    if ((t & 31) == 0) {
        red[wid * 4 + 0] = r0lo;
        red[wid * 4 + 1] = r0hi;
        red[wid * 4 + 2] = r1lo;
        red[wid * 4 + 3] = r1hi;
    }
    __syncthreads();
    if ((t & 63) == 0) {
        int g = t >> 6;
        int ii = by * 4 + g;
        int row0 = rp * 2, row1 = rp * 2 + 1;
        g_agg1[(size_t)row0 * Fq + ii]      = red[2 * g * 4 + 0] + red[(2 * g + 1) * 4 + 0];
        g_agg1[(size_t)row0 * Fq + ii + 32] = red[2 * g * 4 + 1] + red[(2 * g + 1) * 4 + 1];
        g_agg1[(size_t)row1 * Fq + ii]      = red[2 * g * 4 + 2] + red[(2 * g + 1) * 4 + 2];
        g_agg1[(size_t)row1 * Fq + ii + 32] = red[2 * g * 4 + 3] + red[(2 * g + 1) * 4 + 3];
    }
}

// ---------------------------------------------------------------------------
// Kernel 2: round-1 GRU only (agg precomputed). 384 threads:
// xg1 (t<192) and xg2 (t>=192) matvecs run in PARALLEL over the same gk.
// Reads g_H (H0) + g_agg1; writes g_H2 (H1).
// ---------------------------------------------------------------------------
__global__ __launch_bounds__(384) void k_gru1(
    const float* __restrict__ gk, const float* __restrict__ grk,
    const float* __restrict__ gb, const float* __restrict__ grb)
{
    int row = blockIdx.x;
    int t = threadIdx.x;

    __shared__ float xold[Fq], aggv[Fq], h1[Fq];
    __shared__ float xg1[3 * Fq], xg2[3 * Fq], hg2[3 * Fq];

    if (t < 64) xold[t] = g_H[(size_t)row * Fq + t];
    else if (t < 128) aggv[t - 64] = g_agg1[(size_t)row * Fq + (t - 64)];
    __syncthreads();

    if (t < 192) {
        float a = gb[t];
#pragma unroll 8
        for (int j = 0; j < Fq; j++) a += xold[j] * gk[j * 192 + t];
        xg1[t] = a;
    } else {
        int o = t - 192;
        float a = gb[o];
#pragma unroll 8
        for (int j = 0; j < Fq; j++) a += aggv[j] * gk[j * 192 + o];
        xg2[o] = a;
    }
    __syncthreads();
    if (t < Fq) {
        float z = sigm(xg1[t] + grb[t]);
        float r = sigm(xg1[Fq + t] + grb[Fq + t]);
        float cand = tanhf(xg1[2 * Fq + t] + r * grb[2 * Fq + t]);
        h1[t] = (1.0f - z) * cand;
    }
    __syncthreads();
    if (t < 192) {
        float hh = grb[t];
#pragma unroll 8
        for (int j = 0; j < Fq; j++) hh += h1[j] * grk[j * 192 + t];
        hg2[t] = hh;
    }
    __syncthreads();
    if (t < Fq) {
        float z = sigm(xg2[t] + hg2[t]);
        float r = sigm(xg2[Fq + t] + hg2[Fq + t]);
        float cand = tanhf(xg2[2 * Fq + t] + r * hg2[2 * Fq + t]);
        g_H2[(size_t)row * Fq + t] = z * h1[t] + (1.0f - z) * cand;
    }
}

// ---------------------------------------------------------------------------
// Kernel 3: one full round (rounds 2 & 3): cp.async 4-stage pipeline + GRU.
// Identical to the proven R8 version.
// ---------------------------------------------------------------------------
constexpr int SMEM_STAGE = NSTAGE * CHUNK_BYTES;                  // 65536
constexpr int SMEM_HS    = (Nq + 1) * Fq * 4;                     // 16640
constexpr int SMEM_FLT   = (64 * 3 + 128 + 192 * 3) * 4;          // 3584
constexpr int SMEM_TOTAL = SMEM_STAGE + SMEM_HS + SMEM_FLT;       // 85760

__global__ __launch_bounds__(512) void k_round(
    const float* __restrict__ Hin, float* __restrict__ Hout,
    const float* __restrict__ gk, const float* __restrict__ grk,
    const float* __restrict__ gb, const float* __restrict__ grb)
{
    extern __shared__ __align__(16) char smem[];
    char* stage = smem;
    __half2 (*hs2)[Fq] = reinterpret_cast<__half2(*)[Fq]>(smem + SMEM_STAGE);
    float* fl   = reinterpret_cast<float*>(smem + SMEM_STAGE + SMEM_HS);
    float* xold = fl;
    float* aggv = fl + 64;
    float* h1   = fl + 128;
    float* aggp = fl + 192;
    float* xg1  = fl + 320;
    float* xg2  = fl + 512;
    float* hg2  = fl + 704;

    int row = blockIdx.x;
    int b = row >> 6;
    int t = threadIdx.x;
    int ee = t >> 8;
    int tt = t & 255;
    int ii = tt >> 3, jq = tt & 7;

    int cnt = g_cnt[row];
    int nchunk = (cnt + 1) >> 1;

    const char* Asrc = reinterpret_cast<const char*>(g_Amat)
                     + (size_t)row * Nq * 8192;

    auto issue = [&](int c) {
        const char* src = Asrc + (size_t)c * CHUNK_BYTES;
        char* dst = stage + (c & (NSTAGE - 1)) * CHUNK_BYTES;
        cp_async16(dst + t * 16, src + t * 16);
        cp_async16(dst + t * 16 + 8192, src + t * 16 + 8192);
    };

#pragma unroll
    for (int s = 0; s < NSTAGE - 1; s++) {
        if (s < nchunk) issue(s);
        cp_commit();
    }

    for (int idx = t; idx < cnt * Fq; idx += 512) {
        int e = idx >> 6, j = idx & 63;
        int m = g_midx[row * Nq + e];
        float v = Hin[((size_t)b * Nq + m) * Fq + j];
        hs2[e][j] = __float2half2_rn(v);
    }
    if (t < Fq) hs2[cnt][t] = __float2half2_rn(0.0f);
    if (t >= 64 && t < 128) xold[t - 64] = Hin[(size_t)row * Fq + (t - 64)];

    float flo = 0.0f, fhi = 0.0f;

    for (int c = 0; c < nchunk; c++) {
        cp_wait<NSTAGE - 2>();
        __syncthreads();

        const uint4* ap = reinterpret_cast<const uint4*>(
            stage + (c & (NSTAGE - 1)) * CHUNK_BYTES) + ee * 512 + ii * 16 + jq * 2;
        uint4 a0 = ap[0];
        uint4 a1 = ap[1];
        int e = 2 * c + ee;
        const uint4* hp = reinterpret_cast<const uint4*>(&hs2[e][jq * 8]);
        uint4 hA = hp[0];
        uint4 hB = hp[1];
        __half2 cA = __hmul2(h2(a0.x), h2(hA.x));
        cA = __hfma2(h2(a0.y), h2(hA.y), cA);
        cA = __hfma2(h2(a0.z), h2(hA.z), cA);
        cA = __hfma2(h2(a0.w), h2(hA.w), cA);
        __half2 cB = __hmul2(h2(a1.x), h2(hB.x));
        cB = __hfma2(h2(a1.y), h2(hB.y), cB);
        cB = __hfma2(h2(a1.z), h2(hB.z), cB);
        cB = __hfma2(h2(a1.w), h2(hB.w), cB);
        float2 f = __half22float2(__hadd2(cA, cB));
        flo += f.x;
        fhi += f.y;

        int nx = c + NSTAGE - 1;
        if (nx < nchunk) issue(nx);
        cp_commit();
    }
    cp_wait<0>();

    flo += __shfl_xor_sync(0xffffffffu, flo, 1);
    flo += __shfl_xor_sync(0xffffffffu, flo, 2);
    flo += __shfl_xor_sync(0xffffffffu, flo, 4);
    fhi += __shfl_xor_sync(0xffffffffu, fhi, 1);
    fhi += __shfl_xor_sync(0xffffffffu, fhi, 2);
    fhi += __shfl_xor_sync(0xffffffffu, fhi, 4);
    if (jq == 0) {
        aggp[ee * 64 + ii] = flo;
        aggp[ee * 64 + ii + 32] = fhi;
    }
    __syncthreads();
    if (t < Fq) aggv[t] = aggp[t] + aggp[64 + t];
    __syncthreads();

    if (t < 192) {
        float a1 = gb[t], a2 = gb[t];
#pragma unroll 8
        for (int j = 0; j < Fq; j++) {
            float wv = gk[j * 192 + t];
            a1 += xold[j] * wv;
            a2 += aggv[j] * wv;
        }
        xg1[t] = a1;
        xg2[t] = a2;
    }
    __syncthreads();
    if (t < Fq) {
        float z = sigm(xg1[t] + grb[t]);
        float rr = sigm(xg1[Fq + t] + grb[Fq + t]);
        float cand = tanhf(xg1[2 * Fq + t] + rr * grb[2 * Fq + t]);
        h1[t] = (1.0f - z) * cand;
    }
    __syncthreads();
    if (t < 192) {
        float hh = grb[t];
#pragma unroll 8
        for (int j = 0; j < Fq; j++) hh += h1[j] * grk[j * 192 + t];
        hg2[t] = hh;
    }
    __syncthreads();
    if (t < Fq) {
        float z = sigm(xg2[t] + hg2[t]);
        float rr = sigm(xg2[Fq + t] + hg2[Fq + t]);
        float cand = tanhf(xg2[2 * Fq + t] + rr * hg2[2 * Fq + t]);
        Hout[(size_t)row * Fq + t] = z * h1[t] + (1.0f - z) * cand;
    }
}

// ---------------------------------------------------------------------------
extern "C" void kernel_launch(void* const* d_in, const int* in_sizes, int n_in,
                              void* d_out, int out_size)
{
    const float* X       = (const float*)d_in[0];
    const float* A       = (const float*)d_in[1];
    const float* E       = (const float*)d_in[2];
    const float* W_embed = (const float*)d_in[3];
    const float* b_embed = (const float*)d_in[4];
    const float* W_edge  = (const float*)d_in[5];
    const float* b_edge  = (const float*)d_in[6];
    const float* gk      = (const float*)d_in[7];
    const float* grk     = (const float*)d_in[8];
    const float* gb      = (const float*)d_in[9];
    const float* grb     = (const float*)d_in[10];
    float* out = (float*)d_out;

    float *hbuf = nullptr, *h2buf = nullptr;
    cudaGetSymbolAddress((void**)&hbuf, g_H);
    cudaGetSymbolAddress((void**)&h2buf, g_H2);

    static bool attr_set = false;
    if (!attr_set) {
        cudaFuncSetAttribute(k_round, cudaFuncAttributeMaxDynamicSharedMemorySize,
                             SMEM_TOTAL);
        cudaFuncSetAttribute(k_edge, cudaFuncAttributeMaxDynamicSharedMemorySize,
                             ESM_TOTAL);
        attr_set = true;
    }

    // edge MLP + embed + compaction + round-1 aggregation
    k_edge<<<dim3(ROWS / 2, 8), 256, ESM_TOTAL>>>(X, A, E, W_embed, b_embed,
                                                  W_edge, b_edge);
    // round 1 = GRU only
    k_gru1<<<ROWS, 384>>>(gk, grk, gb, grb);
    // rounds 2 and 3 (full)
    k_round<<<ROWS, 512, SMEM_TOTAL>>>(h2buf, hbuf, gk, grk, gb, grb);
    k_round<<<ROWS, 512, SMEM_TOTAL>>>(hbuf, out,  gk, grk, gb, grb);
}

// round 11
// speedup vs baseline: 1.3065x; 1.3065x over previous
#include <cuda_runtime.h>
#include <cuda_fp16.h>
#include <math.h>

constexpr int Bq   = 4;
constexpr int Nq   = 64;
constexpr int Fq   = 64;
constexpr int FINq = 32;
constexpr int EDIMq= 32;
constexpr int FFq  = Fq * Fq;          // 4096
constexpr int ROWS = Bq * Nq;          // 256 target rows (b,n)

constexpr int NBLK = 128;              // persistent blocks (1/SM, co-resident)
constexpr int CAP  = 21;               // retained edge slots per block
constexpr int NRING= 4;                // stream ring stages (8KB each)

__device__ float  g_H[ROWS * Fq];
__device__ float  g_H2[ROWS * Fq];
__device__ int    g_cnt[ROWS];
__device__ int    g_midx[ROWS * Nq];
// Interleaved: per slot 2048 half2; entry c (c = ii*64+j, ii<32) holds
// (A[ii][j], A[ii+32][j]). Inactive slots stay zero (never written).
__device__ __align__(16) __half2 g_Amat[(size_t)ROWS * Nq * (FFq / 2)];

__device__ int          g_bar_count = 0;
__device__ volatile int g_bar_gen   = 0;

__device__ __forceinline__ float sigm(float x) { return 1.0f / (1.0f + expf(-x)); }
__device__ __forceinline__ __half2 h2(unsigned int u) {
    return *reinterpret_cast<__half2*>(&u);
}
__device__ __forceinline__ unsigned long long pack2(float lo, float hi) {
    unsigned long long r;
    asm("mov.b64 %0, {%1, %2};" : "=l"(r) : "f"(lo), "f"(hi));
    return r;
}
__device__ __forceinline__ void unpack2(unsigned long long v, float& lo, float& hi) {
    asm("mov.b64 {%0, %1}, %2;" : "=f"(lo), "=f"(hi) : "l"(v));
}
__device__ __forceinline__ unsigned long long ffma2(
    unsigned long long a, unsigned long long b, unsigned long long c) {
    unsigned long long d;
    asm("fma.rn.f32x2 %0, %1, %2, %3;" : "=l"(d) : "l"(a), "l"(b), "l"(c));
    return d;
}
__device__ __forceinline__ void cp_async16(void* smem_ptr, const void* gptr) {
    unsigned sa = (unsigned)__cvta_generic_to_shared(smem_ptr);
    asm volatile("cp.async.cg.shared.global [%0], [%1], 16;" :: "r"(sa), "l"(gptr));
}
__device__ __forceinline__ void cp_commit() {
    asm volatile("cp.async.commit_group;");
}
template<int N> __device__ __forceinline__ void cp_wait() {
    asm volatile("cp.async.wait_group %0;" :: "n"(N));
}

__device__ __forceinline__ void grid_barrier() {
    __threadfence();
    __syncthreads();
    if (threadIdx.x == 0) {
        int gen = g_bar_gen;
        if (atomicAdd(&g_bar_count, 1) == NBLK - 1) {
            g_bar_count = 0;
            __threadfence();
            g_bar_gen = gen + 1;
        } else {
            while (g_bar_gen == gen) { }
        }
    }
    __syncthreads();
}

// ---------------------------------------------------------------------------
// Kernel 1: edge MLP (with its own ballot compaction). Interleaved fp16 out.
// Block (rp, by): rows {2rp, 2rp+1} x column pairs (c0+t, c0+t+2048).
// by==0 blocks publish g_cnt / g_midx for k_rounds.
// ---------------------------------------------------------------------------
__global__ __launch_bounds__(256) void k_edge(
    const float* __restrict__ A, const float* __restrict__ E,
    const float* __restrict__ W_edge, const float* __restrict__ b_edge)
{
    __shared__ unsigned long long Es2[128 * EDIMq];   // 32KB
    __shared__ int s_m[128];
    __shared__ int s_cnt[2];

    int rp = blockIdx.x, by = blockIdx.y, c0 = by * 256, t = threadIdx.x;

    if (t < 64) {
        int r = t >> 5, lane = t & 31;
        int row = rp * 2 + r;
        const float* Arow = A + (size_t)row * Nq;
        unsigned a0 = (Arow[lane] > 0.5f) ? 1u : 0u;
        unsigned a1 = (Arow[32 + lane] > 0.5f) ? 1u : 0u;
        unsigned m0 = __ballot_sync(0xffffffffu, a0);
        unsigned m1 = __ballot_sync(0xffffffffu, a1);
        unsigned lm = (lane == 0) ? 0u : (0xffffffffu >> (32 - lane));
        int n0 = __popc(m0);
        if (a0) { int p = __popc(m0 & lm); s_m[r * 64 + p] = lane;
                  if (by == 0) g_midx[row * Nq + p] = lane; }
        if (a1) { int p = n0 + __popc(m1 & lm); s_m[r * 64 + p] = 32 + lane;
                  if (by == 0) g_midx[row * Nq + p] = 32 + lane; }
        if (lane == 0) { int c = n0 + __popc(m1); s_cnt[r] = c;
                         if (by == 0) g_cnt[row] = c; }
    }
    __syncthreads();
    int cnt0 = s_cnt[0], ne = cnt0 + s_cnt[1];

    for (int i = t; i < ne * EDIMq; i += 256) {
        int kk = i >> 5, e = i & 31;
        int p  = (kk >= cnt0) ? 1 : 0;
        int kl = kk - (p ? cnt0 : 0);
        int row = rp * 2 + p;
        int m  = s_m[p * 64 + kl];
        float v = E[((size_t)row * Nq + m) * EDIMq + e];
        Es2[kk * EDIMq + e] = pack2(v, v);
    }
    __syncthreads();

    int c_a = c0 + t, c_b = c_a + 2048;
    unsigned long long w01[EDIMq];
#pragma unroll
    for (int e = 0; e < EDIMq; e++)
        w01[e] = pack2(W_edge[(size_t)e * FFq + c_a], W_edge[(size_t)e * FFq + c_b]);
    unsigned long long bias01 = pack2(b_edge[c_a], b_edge[c_b]);

    auto emit = [&](int kk, unsigned long long acc) {
        float a0, a1;
        unpack2(acc, a0, a1);
        int p  = (kk >= cnt0) ? 1 : 0;
        int kl = kk - (p ? cnt0 : 0);
        size_t slot = (size_t)(rp * 2 + p) * Nq + kl;
        g_Amat[slot * (FFq / 2) + c_a] =
            __floats2half2_rn(fmaxf(a0, 0.0f), fmaxf(a1, 0.0f));
    };

    int kk = 0;
    for (; kk + 2 <= ne; kk += 2) {
        unsigned long long acc0 = bias01, acc1 = bias01;
#pragma unroll
        for (int e = 0; e < EDIMq; e++) {
            acc0 = ffma2(Es2[kk * EDIMq + e],       w01[e], acc0);
            acc1 = ffma2(Es2[(kk + 1) * EDIMq + e], w01[e], acc1);
        }
        emit(kk, acc0);
        emit(kk + 1, acc1);
    }
    if (kk < ne) {
        unsigned long long acc0 = bias01;
#pragma unroll
        for (int e = 0; e < EDIMq; e++)
            acc0 = ffma2(Es2[kk * EDIMq + e], w01[e], acc0);
        emit(kk, acc0);
    }
}

// ---------------------------------------------------------------------------
// Kernel 2: persistent rounds. 128 blocks x 512 threads, 1/SM.
// Block owns rows {2bid, 2bid+1}: preloads up to CAP edge slots into SMEM
// (kept across ALL rounds), streams only the overflow each round, computes
// the embedding locally (round 1 needs no global H), grid barrier between
// rounds. Thread map: ii = t>>4 (feature pair ii/ii+32), jj = (t&15)*4.
// ---------------------------------------------------------------------------
constexpr int AMAT_OFF = 0;                            // CAP*8192      = 172032
constexpr int RING_OFF = CAP * 8192;                   // NRING*8192    = 32768
constexpr int HS_OFF   = RING_OFF + NRING * 8192;      // 64*64*4       = 16384
constexpr int FLT_OFF  = HS_OFF + Nq * Fq * 4;         // 1536 floats   = 6144
constexpr int SM_OFF   = FLT_OFF + 1536 * 4;           // 128 ints      = 512
constexpr int KSM_TOTAL= SM_OFF + 512;                 // 227,840 bytes

__global__ __launch_bounds__(512) void k_rounds(
    const float* __restrict__ X,
    const float* __restrict__ W_embed, const float* __restrict__ b_embed,
    const float* __restrict__ gk, const float* __restrict__ grk,
    const float* __restrict__ gb, const float* __restrict__ grb,
    float* __restrict__ out)
{
    extern __shared__ __align__(16) char smem[];
    char*    AmatS = smem + AMAT_OFF;
    char*    ring  = smem + RING_OFF;
    __half2* hs2   = reinterpret_cast<__half2*>(smem + HS_OFF);
    float*   fl    = reinterpret_cast<float*>(smem + FLT_OFF);
    float* xoldA = fl;            // 128
    float* aggvA = fl + 128;      // 128
    float* h1A   = fl + 256;      // 128
    float* xg1   = fl + 384;      // 384
    float* xg2   = fl + 768;      // 384
    float* hg2   = fl + 1152;     // 384
    int*   s_m   = reinterpret_cast<int*>(smem + SM_OFF);

    int bid = blockIdx.x, t = threadIdx.x;
    int r0 = 2 * bid;
    int b  = r0 >> 6;
    int cnt0 = g_cnt[r0], cnt1 = g_cnt[r0 + 1];
    int k0 = min(cnt0, CAP);
    int k1 = min(cnt1, CAP - k0);

    // ---- preload retained slots (fire-and-forget while we embed) ----
    for (int s = 0; s < k0 + k1; s++) {
        size_t slot = (s < k0) ? ((size_t)r0 * Nq + s)
                               : ((size_t)(r0 + 1) * Nq + (s - k0));
        cp_async16(AmatS + (size_t)s * 8192 + t * 16,
                   (const char*)g_Amat + slot * 8192 + t * 16);
    }
    cp_commit();

    // ---- stage compaction indices and X ----
    if (t < 128) s_m[t] = g_midx[(size_t)(r0 + (t >> 6)) * Nq + (t & 63)];
    float* Xs = reinterpret_cast<float*>(ring);        // ring reused pre-stream
    for (int i = t; i < Nq * FINq; i += 512) Xs[i] = X[(size_t)b * Nq * FINq + i];
    __syncthreads();

    // ---- local embedding: hs2 (all 64 batch nodes) + xoldA (own rows) ----
    int n0l = r0 & 63;
    for (int idx = t; idx < Nq * Fq; idx += 512) {
        int m = idx >> 6, f = idx & 63;
        float acc = b_embed[f];
#pragma unroll
        for (int k = 0; k < FINq; k++) acc += Xs[m * FINq + k] * W_embed[k * Fq + f];
        float h0 = fmaxf(acc, 0.0f);
        hs2[idx] = __float2half2_rn(h0);
        if (m == n0l)     xoldA[f]      = h0;
        if (m == n0l + 1) xoldA[64 + f] = h0;
    }
    __syncthreads();
    cp_wait<0>();
    __syncthreads();

    int ii = t >> 4, jj = (t & 15) * 4;

    for (int r = 0; r < 3; r++) {
        if (r > 0) {
            const float* Hp = (r == 1) ? g_H : g_H2;
            for (int i = t; i < Nq * Fq; i += 512)
                hs2[i] = __float2half2_rn(__ldcg(&Hp[(size_t)b * Nq * Fq + i]));
            if (t < 128) xoldA[t] = __ldcg(&Hp[(size_t)r0 * Fq + t]);
            __syncthreads();
        }

        for (int ro = 0; ro < 2; ro++) {
            int cnt  = ro ? cnt1 : cnt0;
            int kret = ro ? k1 : k0;
            int rbase= ro ? k0 : 0;
            float flo = 0.0f, fhi = 0.0f;

            // retained (SMEM-resident across all rounds)
            for (int e = 0; e < kret; e++) {
                int m = s_m[ro * 64 + e];
                uint4 a  = *(const uint4*)(AmatS + (size_t)(rbase + e) * 8192
                                           + (ii * 64 + jj) * 4);
                uint4 hv = *(const uint4*)(hs2 + m * 64 + jj);
                __half2 c2v = __hmul2(h2(a.x), h2(hv.x));
                c2v = __hfma2(h2(a.y), h2(hv.y), c2v);
                c2v = __hfma2(h2(a.z), h2(hv.z), c2v);
                c2v = __hfma2(h2(a.w), h2(hv.w), c2v);
                float2 f2v = __half22float2(c2v);
                flo += f2v.x; fhi += f2v.y;
            }

            // streamed overflow via cp.async ring
            int nov = cnt - kret;
            size_t obase = (size_t)(r0 + ro) * Nq + kret;
#pragma unroll
            for (int s = 0; s < NRING - 1; s++) {
                if (s < nov)
                    cp_async16(ring + (s & (NRING - 1)) * 8192 + t * 16,
                               (const char*)g_Amat + (obase + s) * 8192 + t * 16);
                cp_commit();
            }
            for (int c = 0; c < nov; c++) {
                cp_wait<NRING - 2>();
                __syncthreads();
                int m = s_m[ro * 64 + kret + c];
                uint4 a  = *(const uint4*)(ring + (c & (NRING - 1)) * 8192
                                           + (ii * 64 + jj) * 4);
                uint4 hv = *(const uint4*)(hs2 + m * 64 + jj);
                __half2 c2v = __hmul2(h2(a.x), h2(hv.x));
                c2v = __hfma2(h2(a.y), h2(hv.y), c2v);
                c2v = __hfma2(h2(a.z), h2(hv.z), c2v);
                c2v = __hfma2(h2(a.w), h2(hv.w), c2v);
                float2 f2v = __half22float2(c2v);
                flo += f2v.x; fhi += f2v.y;
                int nx = c + NRING - 1;
                if (nx < nov)
                    cp_async16(ring + (nx & (NRING - 1)) * 8192 + t * 16,
                               (const char*)g_Amat + (obase + nx) * 8192 + t * 16);
                cp_commit();
            }
            cp_wait<0>();

            // reduce over the 16 jj-lanes
#pragma unroll
            for (int o = 1; o < 16; o <<= 1) {
                flo += __shfl_xor_sync(0xffffffffu, flo, o);
                fhi += __shfl_xor_sync(0xffffffffu, fhi, o);
            }
            if ((t & 15) == 0) {
                aggvA[ro * 64 + ii]      = flo;
                aggvA[ro * 64 + ii + 32] = fhi;
            }
            __syncthreads();
        }

        // ---- fused GRU for both rows ----
        if (t < 384) {
            int ro = t / 192, o = t % 192;
            float a1 = gb[o], a2 = gb[o];
#pragma unroll 8
            for (int j = 0; j < Fq; j++) {
                float w = gk[j * 192 + o];
                a1 += xoldA[ro * 64 + j] * w;
                a2 += aggvA[ro * 64 + j] * w;
            }
            xg1[ro * 192 + o] = a1;
            xg2[ro * 192 + o] = a2;
        }
        __syncthreads();
        if (t < 128) {
            int ro = t >> 6, f = t & 63;
            float z  = sigm(xg1[ro * 192 + f] + grb[f]);
            float rr = sigm(xg1[ro * 192 + 64 + f] + grb[64 + f]);
            float cand = tanhf(xg1[ro * 192 + 128 + f] + rr * grb[128 + f]);
            h1A[ro * 64 + f] = (1.0f - z) * cand;
        }
        __syncthreads();
        if (t < 384) {
            int ro = t / 192, o = t % 192;
            float hh = grb[o];
#pragma unroll 8
            for (int j = 0; j < Fq; j++) hh += h1A[ro * 64 + j] * grk[j * 192 + o];
            hg2[ro * 192 + o] = hh;
        }
        __syncthreads();
        float* Hout = (r == 0) ? g_H : ((r == 1) ? g_H2 : out);
        if (t < 128) {
            int ro = t >> 6, f = t & 63;
            float z  = sigm(xg2[ro * 192 + f] + hg2[ro * 192 + f]);
            float rr = sigm(xg2[ro * 192 + 64 + f] + hg2[ro * 192 + 64 + f]);
            float cand = tanhf(xg2[ro * 192 + 128 + f] + rr * hg2[ro * 192 + 128 + f]);
            Hout[(size_t)(r0 + ro) * Fq + f] =
                z * h1A[ro * 64 + f] + (1.0f - z) * cand;
        }

        if (r < 2) grid_barrier();
    }
}

// ---------------------------------------------------------------------------
extern "C" void kernel_launch(void* const* d_in, const int* in_sizes, int n_in,
                              void* d_out, int out_size)
{
    const float* X       = (const float*)d_in[0];
    const float* A       = (const float*)d_in[1];
    const float* E       = (const float*)d_in[2];
    const float* W_embed = (const float*)d_in[3];
    const float* b_embed = (const float*)d_in[4];
    const float* W_edge  = (const float*)d_in[5];
    const float* b_edge  = (const float*)d_in[6];
    const float* gk      = (const float*)d_in[7];
    const float* grk     = (const float*)d_in[8];
    const float* gb      = (const float*)d_in[9];
    const float* grb     = (const float*)d_in[10];
    float* out = (float*)d_out;

    static bool attr_set = false;
    if (!attr_set) {
        cudaFuncSetAttribute(k_rounds, cudaFuncAttributeMaxDynamicSharedMemorySize,
                             KSM_TOTAL);
        attr_set = true;
    }

    k_edge<<<dim3(ROWS / 2, 8), 256>>>(A, E, W_edge, b_edge);
    k_rounds<<<NBLK, 512, KSM_TOTAL>>>(X, W_embed, b_embed,
                                       gk, grk, gb, grb, out);
}